// round 2
// baseline (speedup 1.0000x reference)
#include <cuda_runtime.h>
#include <cuda.h>
#include <cuda_bf16.h>
#include <cuda_fp8.h>
#include <cstdint>

#define DI __device__ __forceinline__

// ---------------- problem dims ----------------
static constexpr int M_DIM = 8192;
static constexpr int N_DIM = 4096;
static constexpr int K_DIM = 4096;

// ---------------- GEMM tiling ----------------
static constexpr int TILE_M = 128;
static constexpr int TILE_N = 256;
static constexpr int KCHUNK = 64;                      // bf16 elems per k-chunk (128B rows, SW128)
static constexpr int NCHUNKS = K_DIM / KCHUNK;         // 64
static constexpr int STAGES  = 3;
static constexpr int A_BYTES = TILE_M * KCHUNK * 2;    // 16 KB per plane
static constexpr int B_BYTES = TILE_N * KCHUNK * 2;    // 32 KB
static constexpr int STAGE_BYTES = 2 * A_BYTES + B_BYTES;             // 64 KB
static constexpr int SMEM_CTRL  = 1024;
static constexpr int SMEM_REQ   = SMEM_CTRL + STAGES * STAGE_BYTES + 1024;

#define OFF_FULL(s)  ((s)*16)
#define OFF_EMPTY(s) ((s)*16 + 8)

// ---------------- device scratch (no cudaMalloc allowed) ----------------
__device__ __align__(1024) __nv_bfloat16 g_wdq[(size_t)N_DIM * K_DIM];   // 32 MB
__device__ __align__(1024) __nv_bfloat16 g_xhi[(size_t)M_DIM * K_DIM];   // 64 MB
__device__ __align__(1024) __nv_bfloat16 g_xlo[(size_t)M_DIM * K_DIM];   // 64 MB

// ---------------- PTX helpers (baseline sm_90/sm_80 features only) ----------------
DI uint32_t smem_u32(const void* p) {
    uint32_t a;
    asm("{ .reg .u64 t; cvta.to.shared.u64 t, %1; cvt.u32.u64 %0, t; }" : "=r"(a) : "l"(p));
    return a;
}

#define MBAR_INIT(mbar, cnt) \
    asm volatile("mbarrier.init.shared.b64 [%0], %1;" :: "r"((uint32_t)(mbar)), "r"((uint32_t)(cnt)) : "memory")
#define MBAR_EXPECT_TX(mbar, bytes) \
    asm volatile("mbarrier.arrive.expect_tx.shared.b64 _, [%0], %1;" \
                 :: "r"((uint32_t)(mbar)), "r"((uint32_t)(bytes)) : "memory")
#define MBAR_ARRIVE(mbar) \
    asm volatile("mbarrier.arrive.shared.b64 _, [%0];" :: "r"((uint32_t)(mbar)) : "memory")
#define MBAR_WAIT(mbar, ph) do { \
    asm volatile("{\n\t.reg .pred P1;\n\t" \
        "WAIT_%=:\n\t" \
        "mbarrier.try_wait.parity.acquire.cta.shared::cta.b64 P1, [%0], %1, 0x989680;\n\t" \
        "@P1 bra.uni DONE_%=;\n\t" \
        "bra.uni WAIT_%=;\n\t" \
        "DONE_%=:\n\t}" :: "r"((uint32_t)(mbar)), "r"((uint32_t)(ph)) : "memory"); \
} while (0)

DI void tma2d(uint32_t dst, const CUtensorMap* map, int cx, int cy, uint32_t mbar) {
    asm volatile(
        "cp.async.bulk.tensor.2d.shared::cta.global.tile.mbarrier::complete_tx::bytes "
        "[%0], [%1, {%2, %3}], [%4];"
        :: "r"(dst), "l"(map), "r"(cx), "r"(cy), "r"(mbar) : "memory");
}

DI void ldsm4(uint32_t* r, uint32_t addr) {
    asm volatile("ldmatrix.sync.aligned.m8n8.x4.shared.b16 {%0,%1,%2,%3}, [%4];"
                 : "=r"(r[0]), "=r"(r[1]), "=r"(r[2]), "=r"(r[3]) : "r"(addr));
}

DI void mma16816(float* d, const uint32_t* a, const uint32_t* b) {
    asm volatile(
        "mma.sync.aligned.m16n8k16.row.col.f32.bf16.bf16.f32 "
        "{%0,%1,%2,%3}, {%4,%5,%6,%7}, {%8,%9}, {%0,%1,%2,%3};"
        : "+f"(d[0]), "+f"(d[1]), "+f"(d[2]), "+f"(d[3])
        : "r"(a[0]), "r"(a[1]), "r"(a[2]), "r"(a[3]), "r"(b[0]), "r"(b[1]));
}

// ---------------- NVFP4 quantizer (warp per 32-block) ----------------
DI float cb_round(float a) {
    // nearest of {0,.5,1,1.5,2,3,4,6}; ties -> lower value (matches argmin-first)
    float r;
    if      (a <= 0.25f) r = 0.0f;
    else if (a <= 0.75f) r = 0.5f;
    else if (a <= 1.25f) r = 1.0f;
    else if (a <= 1.75f) r = 1.5f;
    else if (a <= 2.5f)  r = 2.0f;
    else if (a <= 3.5f)  r = 3.0f;
    else if (a <= 5.0f)  r = 4.0f;
    else                 r = 6.0f;
    return r;
}

__global__ void __launch_bounds__(256) quant_kernel(const float* __restrict__ w,
                                                    __nv_bfloat16* __restrict__ wdq) {
    const int gb   = blockIdx.x * 8 + (threadIdx.x >> 5);   // global 32-block id
    const int lane = threadIdx.x & 31;
    const size_t base = (size_t)gb * 32;
    const float v = w[base + lane];

    float a = fabsf(v);
    #pragma unroll
    for (int o = 16; o > 0; o >>= 1) a = fmaxf(a, __shfl_xor_sync(0xffffffffu, a, o));
    const float bm = fmaxf(a, 1e-12f);

    float best_scale = bm;
    float best_mse = __int_as_float(0x7f800000);  // +inf
    #pragma unroll
    for (int t = 0; t < 10; t++) {
        const float ratio = (float)(0.7 + (double)t * (0.3 / 9.0));
        const float ts = bm * ratio;
        const float inv = 6.0f / ts;
        const float s6  = ts / 6.0f;
        float s = fminf(fmaxf(v * inv, -6.0f), 6.0f);
        float q = copysignf(cb_round(fabsf(s)), s);
        float qt = __fmul_rn(q, s6);
        float dd = __fsub_rn(v, qt);
        float e  = dd * dd;
        #pragma unroll
        for (int o = 16; o > 0; o >>= 1) e += __shfl_xor_sync(0xffffffffu, e, o);
        if (e < best_mse) { best_mse = e; best_scale = ts; }
    }

    const float fs  = fmaxf(best_scale, 1e-12f);
    const float inv = 6.0f / fs;
    float s = fminf(fmaxf(v * inv, -6.0f), 6.0f);
    float q = copysignf(cb_round(fabsf(s)), s);

    __nv_fp8_e4m3 f8 = __nv_fp8_e4m3(best_scale / 6.0f);
    float sf = (float)f8;

    // q*sf has <= 6 significand bits -> exact in bf16
    wdq[base + lane] = __float2bfloat16(q * sf);
}

// ---------------- x -> (hi, lo) bf16 split ----------------
__global__ void __launch_bounds__(256) split_kernel(const float4* __restrict__ x4,
                                                    __nv_bfloat162* __restrict__ hi2,
                                                    __nv_bfloat162* __restrict__ lo2,
                                                    int n4) {
    const int stride = gridDim.x * blockDim.x;
    for (int i = blockIdx.x * blockDim.x + threadIdx.x; i < n4; i += stride) {
        float4 v = x4[i];
        __nv_bfloat16 h0 = __float2bfloat16_rn(v.x);
        __nv_bfloat16 h1 = __float2bfloat16_rn(v.y);
        __nv_bfloat16 h2 = __float2bfloat16_rn(v.z);
        __nv_bfloat16 h3 = __float2bfloat16_rn(v.w);
        float l0 = v.x - __bfloat162float(h0);
        float l1 = v.y - __bfloat162float(h1);
        float l2 = v.z - __bfloat162float(h2);
        float l3 = v.w - __bfloat162float(h3);
        hi2[2 * i]     = __nv_bfloat162(h0, h1);
        hi2[2 * i + 1] = __nv_bfloat162(h2, h3);
        lo2[2 * i]     = __nv_bfloat162(__float2bfloat16_rn(l0), __float2bfloat16_rn(l1));
        lo2[2 * i + 1] = __nv_bfloat162(__float2bfloat16_rn(l2), __float2bfloat16_rn(l3));
    }
}

// ---------------- HMMA GEMM: out[M,N] = (xhi+xlo)[M,K] @ wdq[N,K]^T + bias ----------------
__global__ void __launch_bounds__(256, 1) gemm_kernel(
    const __grid_constant__ CUtensorMap tm_xhi,
    const __grid_constant__ CUtensorMap tm_xlo,
    const __grid_constant__ CUtensorMap tm_w,
    const float* __restrict__ bias,
    float* __restrict__ out)
{
    extern __shared__ char smem_raw[];
    const uint32_t sb = (smem_u32(smem_raw) + 1023u) & ~1023u;   // 1KB align for SW128

    const int tid  = threadIdx.x;
    const int wid  = tid >> 5;
    const int lane = tid & 31;
    const int m0 = (int)(blockIdx.x >> 4) * TILE_M;              // 64 m-tiles
    const int n0 = (int)(blockIdx.x & 15) * TILE_N;              // 16 n-tiles

    if (tid == 0) {
        #pragma unroll
        for (int s = 0; s < STAGES; s++) {
            MBAR_INIT(sb + OFF_FULL(s), 1);
            MBAR_INIT(sb + OFF_EMPTY(s), 8);     // 8 warps arrive
        }
    }
    __syncthreads();

    // prologue: fill all stages
    if (tid == 0) {
        #pragma unroll
        for (int s = 0; s < STAGES; s++) {
            MBAR_EXPECT_TX(sb + OFF_FULL(s), STAGE_BYTES);
            uint32_t st = sb + SMEM_CTRL + s * STAGE_BYTES;
            tma2d(st,               &tm_xhi, s * KCHUNK, m0, sb + OFF_FULL(s));
            tma2d(st + A_BYTES,     &tm_xlo, s * KCHUNK, m0, sb + OFF_FULL(s));
            tma2d(st + 2 * A_BYTES, &tm_w,   s * KCHUNK, n0, sb + OFF_FULL(s));
        }
    }

    // per-thread ldmatrix addressing (SW128: physical = logical ^ ((row&7)<<4))
    const int sel = lane >> 3, l7 = lane & 7;
    const uint32_t xm = (uint32_t)l7 << 4;
    const int mwarp = (wid & 1) * 64;
    const int nwarp = (wid >> 1) * 64;
    const int rA = ((sel & 1) << 3) + l7;            // A: sel0,2 -> rows 0-7; sel1,3 -> rows 8-15
    const uint32_t kbA = (uint32_t)(sel >> 1) << 4;  // A: sel2,3 -> k+8 (16B)
    const int rB = (((sel >> 1) & 1) << 3) + l7;     // B: sel2,3 -> n+8
    const uint32_t kbB = (uint32_t)(sel & 1) << 4;   // B: sel1,3 -> k+8
    uint32_t rowA[4], rowB[4];
    #pragma unroll
    for (int f = 0; f < 4; f++) rowA[f] = (uint32_t)(mwarp + f * 16 + rA) * 128u;
    #pragma unroll
    for (int g = 0; g < 4; g++) rowB[g] = (uint32_t)(nwarp + g * 16 + rB) * 128u + 2u * A_BYTES;

    float d[4][8][4] = {};

    int s = 0;
    uint32_t phf = 0, phe = 0;
    #pragma unroll 1
    for (int i = 0; i < NCHUNKS; i++) {
        MBAR_WAIT(sb + OFF_FULL(s), phf);
        const uint32_t st = sb + SMEM_CTRL + s * STAGE_BYTES;

        #pragma unroll
        for (int kk = 0; kk < KCHUNK / 16; kk++) {
            const uint32_t kb = (uint32_t)kk << 5;          // kk*32 bytes
            uint32_t bb[4][4], aa[4][4];
            #pragma unroll
            for (int g = 0; g < 4; g++) ldsm4(bb[g], st + rowB[g] + ((kb + kbB) ^ xm));
            #pragma unroll
            for (int f = 0; f < 4; f++) ldsm4(aa[f], st + rowA[f] + ((kb + kbA) ^ xm));
            #pragma unroll
            for (int f = 0; f < 4; f++)
                #pragma unroll
                for (int g = 0; g < 4; g++) {
                    mma16816(d[f][2 * g],     aa[f], &bb[g][0]);
                    mma16816(d[f][2 * g + 1], aa[f], &bb[g][2]);
                }
            // lo plane: reuse B fragments
            #pragma unroll
            for (int f = 0; f < 4; f++) ldsm4(aa[f], st + A_BYTES + rowA[f] + ((kb + kbA) ^ xm));
            #pragma unroll
            for (int f = 0; f < 4; f++)
                #pragma unroll
                for (int g = 0; g < 4; g++) {
                    mma16816(d[f][2 * g],     aa[f], &bb[g][0]);
                    mma16816(d[f][2 * g + 1], aa[f], &bb[g][2]);
                }
        }

        __syncwarp();
        if (lane == 0) MBAR_ARRIVE(sb + OFF_EMPTY(s));

        if (tid == 0 && i + STAGES < NCHUNKS) {
            MBAR_WAIT(sb + OFF_EMPTY(s), phe);
            MBAR_EXPECT_TX(sb + OFF_FULL(s), STAGE_BYTES);
            const int c = (i + STAGES) * KCHUNK;
            tma2d(st,               &tm_xhi, c, m0, sb + OFF_FULL(s));
            tma2d(st + A_BYTES,     &tm_xlo, c, m0, sb + OFF_FULL(s));
            tma2d(st + 2 * A_BYTES, &tm_w,   c, n0, sb + OFF_FULL(s));
        }
        if (++s == STAGES) { s = 0; phf ^= 1; phe ^= 1; }
    }

    // ---- epilogue: registers -> gmem, add bias ----
    const int g2 = lane >> 2, tg = lane & 3;
    float bv0[8], bv1[8];
    #pragma unroll
    for (int nf = 0; nf < 8; nf++) {
        const int n = n0 + nwarp + nf * 8 + tg * 2;
        bv0[nf] = bias[n];
        bv1[nf] = bias[n + 1];
    }
    #pragma unroll
    for (int f = 0; f < 4; f++) {
        const int mrow = m0 + mwarp + f * 16 + g2;
        #pragma unroll
        for (int nf = 0; nf < 8; nf++) {
            const int n = n0 + nwarp + nf * 8 + tg * 2;
            float2 v0 = make_float2(d[f][nf][0] + bv0[nf], d[f][nf][1] + bv1[nf]);
            float2 v1 = make_float2(d[f][nf][2] + bv0[nf], d[f][nf][3] + bv1[nf]);
            *reinterpret_cast<float2*>(&out[(size_t)mrow * N_DIM + n]) = v0;
            *reinterpret_cast<float2*>(&out[(size_t)(mrow + 8) * N_DIM + n]) = v1;
        }
    }
}

// ---------------- host ----------------
typedef CUresult (*PFN_EncodeTiled)(
    CUtensorMap*, CUtensorMapDataType, cuuint32_t, void*,
    const cuuint64_t*, const cuuint64_t*, const cuuint32_t*, const cuuint32_t*,
    CUtensorMapInterleave, CUtensorMapSwizzle, CUtensorMapL2promotion, CUtensorMapFloatOOBfill);

static void make_map_2d(PFN_EncodeTiled fn, CUtensorMap* m, void* ptr,
                        uint64_t rows, uint32_t boxRows) {
    cuuint64_t dims[2]    = {(cuuint64_t)K_DIM, (cuuint64_t)rows};
    cuuint64_t strides[1] = {(cuuint64_t)K_DIM * 2};
    cuuint32_t box[2]     = {(cuuint32_t)KCHUNK, boxRows};   // 64 bf16 = 128B (SW128 limit)
    cuuint32_t es[2]      = {1, 1};
    fn(m, CU_TENSOR_MAP_DATA_TYPE_BFLOAT16, 2, ptr, dims, strides, box, es,
       CU_TENSOR_MAP_INTERLEAVE_NONE, CU_TENSOR_MAP_SWIZZLE_128B,
       CU_TENSOR_MAP_L2_PROMOTION_L2_128B, CU_TENSOR_MAP_FLOAT_OOB_FILL_NONE);
}

extern "C" void kernel_launch(void* const* d_in, const int* in_sizes, int n_in,
                              void* d_out, int out_size) {
    const float* x    = (const float*)d_in[0];
    const float* w    = (const float*)d_in[1];
    const float* bias = (const float*)d_in[2];
    float* out = (float*)d_out;

    void *p_wdq, *p_xhi, *p_xlo;
    cudaGetSymbolAddress(&p_wdq, g_wdq);
    cudaGetSymbolAddress(&p_xhi, g_xhi);
    cudaGetSymbolAddress(&p_xlo, g_xlo);

    // 1) quantize weight -> exact bf16 dequant plane
    quant_kernel<<<(N_DIM * K_DIM / 32) / 8, 256>>>(w, (__nv_bfloat16*)p_wdq);

    // 2) split x into bf16 hi/lo planes
    split_kernel<<<4096, 256>>>((const float4*)x, (__nv_bfloat162*)p_xhi,
                                (__nv_bfloat162*)p_xlo, M_DIM * K_DIM / 4);

    // 3) tensor maps (driver entry point fetched via runtime; no -lcuda needed)
    PFN_EncodeTiled fn = nullptr;
    cudaDriverEntryPointQueryResult qres;
    cudaGetDriverEntryPointByVersion("cuTensorMapEncodeTiled", (void**)&fn, 12000,
                                     cudaEnableDefault, &qres);
    if (!fn) return;

    CUtensorMap tm_xhi, tm_xlo, tm_w;
    make_map_2d(fn, &tm_xhi, p_xhi, M_DIM, TILE_M);
    make_map_2d(fn, &tm_xlo, p_xlo, M_DIM, TILE_M);
    make_map_2d(fn, &tm_w,   p_wdq, N_DIM, TILE_N);

    cudaFuncSetAttribute(gemm_kernel, cudaFuncAttributeMaxDynamicSharedMemorySize, SMEM_REQ);
    gemm_kernel<<<(M_DIM / TILE_M) * (N_DIM / TILE_N), 256, SMEM_REQ>>>(
        tm_xhi, tm_xlo, tm_w, bias, out);
}

// round 3
// speedup vs baseline: 2.1795x; 2.1795x over previous
#include <cuda_runtime.h>
#include <cuda.h>
#include <cuda_fp16.h>
#include <cuda_fp8.h>
#include <cstdint>

#define DI __device__ __forceinline__

// ---------------- problem dims ----------------
static constexpr int M_DIM = 8192;
static constexpr int N_DIM = 4096;
static constexpr int K_DIM = 4096;

// ---------------- GEMM tiling ----------------
static constexpr int TILE_M = 128;
static constexpr int TILE_N = 256;
static constexpr int KCHUNK = 64;                      // fp16 elems per k-chunk (128B rows, SW128)
static constexpr int NCHUNKS = K_DIM / KCHUNK;         // 64
static constexpr int STAGES  = 4;
static constexpr int A_BYTES = TILE_M * KCHUNK * 2;    // 16 KB
static constexpr int B_BYTES = TILE_N * KCHUNK * 2;    // 32 KB
static constexpr int STAGE_BYTES = A_BYTES + B_BYTES;  // 48 KB
static constexpr int SMEM_CTRL  = 1024;
static constexpr int SMEM_REQ   = SMEM_CTRL + STAGES * STAGE_BYTES + 1024;  // ~199 KB

#define OFF_FULL(s)  ((s)*16)
#define OFF_EMPTY(s) ((s)*16 + 8)

// ---------------- device scratch (no cudaMalloc allowed) ----------------
__device__ __align__(1024) __half g_wdq[(size_t)N_DIM * K_DIM];   // 32 MB
__device__ __align__(1024) __half g_xh[(size_t)M_DIM * K_DIM];    // 64 MB

// ---------------- PTX helpers ----------------
DI uint32_t smem_u32(const void* p) {
    uint32_t a;
    asm("{ .reg .u64 t; cvta.to.shared.u64 t, %1; cvt.u32.u64 %0, t; }" : "=r"(a) : "l"(p));
    return a;
}

#define MBAR_INIT(mbar, cnt) \
    asm volatile("mbarrier.init.shared.b64 [%0], %1;" :: "r"((uint32_t)(mbar)), "r"((uint32_t)(cnt)) : "memory")
#define MBAR_EXPECT_TX(mbar, bytes) \
    asm volatile("mbarrier.arrive.expect_tx.shared.b64 _, [%0], %1;" \
                 :: "r"((uint32_t)(mbar)), "r"((uint32_t)(bytes)) : "memory")
#define MBAR_ARRIVE(mbar) \
    asm volatile("mbarrier.arrive.shared.b64 _, [%0];" :: "r"((uint32_t)(mbar)) : "memory")
#define MBAR_WAIT(mbar, ph) do { \
    asm volatile("{\n\t.reg .pred P1;\n\t" \
        "WAIT_%=:\n\t" \
        "mbarrier.try_wait.parity.acquire.cta.shared::cta.b64 P1, [%0], %1, 0x989680;\n\t" \
        "@P1 bra.uni DONE_%=;\n\t" \
        "bra.uni WAIT_%=;\n\t" \
        "DONE_%=:\n\t}" :: "r"((uint32_t)(mbar)), "r"((uint32_t)(ph)) : "memory"); \
} while (0)

DI void tma2d(uint32_t dst, const CUtensorMap* map, int cx, int cy, uint32_t mbar) {
    asm volatile(
        "cp.async.bulk.tensor.2d.shared::cta.global.tile.mbarrier::complete_tx::bytes "
        "[%0], [%1, {%2, %3}], [%4];"
        :: "r"(dst), "l"(map), "r"(cx), "r"(cy), "r"(mbar) : "memory");
}

DI void ldsm4(uint32_t* r, uint32_t addr) {
    asm volatile("ldmatrix.sync.aligned.m8n8.x4.shared.b16 {%0,%1,%2,%3}, [%4];"
                 : "=r"(r[0]), "=r"(r[1]), "=r"(r[2]), "=r"(r[3]) : "r"(addr));
}

DI void mma16816(float* d, const uint32_t* a, const uint32_t* b) {
    asm volatile(
        "mma.sync.aligned.m16n8k16.row.col.f32.f16.f16.f32 "
        "{%0,%1,%2,%3}, {%4,%5,%6,%7}, {%8,%9}, {%0,%1,%2,%3};"
        : "+f"(d[0]), "+f"(d[1]), "+f"(d[2]), "+f"(d[3])
        : "r"(a[0]), "r"(a[1]), "r"(a[2]), "r"(a[3]), "r"(b[0]), "r"(b[1]));
}

// ---------------- codebook round (ties toward lower value, matching argmin) ----------------
DI float cb_round(float a) {
    // a >= 0 (possibly > 6; then -> 6, which equals clip-then-round)
    float q1 = ceilf(__fmaf_rn(2.0f, a, -0.5f)) * 0.5f;   // a in [0,2]: half-steps, tie-down
    float q2 = ceilf(a - 0.5f);                            // a in (2,4]: unit steps, tie-down
    float q3 = (a <= 5.0f) ? 4.0f : 6.0f;                  // a in (4,inf): 4 or 6, tie at 5 -> 4
    return (a <= 2.0f) ? q1 : ((a <= 4.0f) ? q2 : q3);
}

// ---------------- NVFP4 quantizer: 4 threads per 32-block, 8 elems/thread ----------------
__global__ void __launch_bounds__(256) quant_kernel(const float4* __restrict__ w4,
                                                    uint4* __restrict__ wdq) {
    const int t = blockIdx.x * 256 + threadIdx.x;     // one thread = 8 elements
    const float4 va = w4[2 * t];
    const float4 vb = w4[2 * t + 1];
    float v[8]  = {va.x, va.y, va.z, va.w, vb.x, vb.y, vb.z, vb.w};
    float av[8];
    #pragma unroll
    for (int j = 0; j < 8; j++) av[j] = fabsf(v[j]);

    // block max over 32 elements = 4 threads (quad butterfly)
    float mx = av[0];
    #pragma unroll
    for (int j = 1; j < 8; j++) mx = fmaxf(mx, av[j]);
    mx = fmaxf(mx, __shfl_xor_sync(0xffffffffu, mx, 1));
    mx = fmaxf(mx, __shfl_xor_sync(0xffffffffu, mx, 2));
    const float bm = fmaxf(mx, 1e-12f);
    const float rinv = 1.0f / bm;                      // single division per thread

    float best_mse = __int_as_float(0x7f800000);       // +inf
    float best_inv = 0.0f, best_s6 = 0.0f;

    #pragma unroll
    for (int ti = 0; ti < 10; ti++) {
        const double rd = (ti == 9) ? 1.0 : (0.7 + (double)ti * (0.3 / 9.0));
        const float rf = (float)rd;                    // compile-time constant
        const float inv = rinv * (6.0f / rf);          // 6/(bm*ratio), constants folded
        const float s6  = bm * (rf / 6.0f);            // ratio*bm/6

        float e = 0.0f;
        #pragma unroll
        for (int j = 0; j < 8; j++) {
            float s = av[j] * inv;                     // scaled magnitude (no clamp needed)
            float q = cb_round(s);
            float d = s - q;
            e = __fmaf_rn(d, d, e);
        }
        // sum over the 4-thread quad, scale back to original domain
        e += __shfl_xor_sync(0xffffffffu, e, 1);
        e += __shfl_xor_sync(0xffffffffu, e, 2);
        float em = e * (s6 * s6);
        if (em < best_mse) { best_mse = em; best_inv = inv; best_s6 = s6; }
    }

    // ue4m3 scale round-trip (matches reference astype(float8_e4m3fn))
    const float sf = (float)__nv_fp8_e4m3(best_s6);

    __half h[8];
    #pragma unroll
    for (int j = 0; j < 8; j++) {
        float q = copysignf(cb_round(av[j] * best_inv), v[j]);
        h[j] = __float2half_rn(q * sf);                // <=5 significand bits: exact in fp16
    }
    uint4 o;
    o.x = *reinterpret_cast<uint32_t*>(&h[0]);
    o.y = *reinterpret_cast<uint32_t*>(&h[2]);
    o.z = *reinterpret_cast<uint32_t*>(&h[4]);
    o.w = *reinterpret_cast<uint32_t*>(&h[6]);
    wdq[t] = o;
}

// ---------------- x -> fp16 ----------------
__global__ void __launch_bounds__(256) convert_kernel(const float4* __restrict__ x4,
                                                      uint4* __restrict__ xh) {
    const int t = blockIdx.x * 256 + threadIdx.x;
    float4 a = x4[2 * t], b = x4[2 * t + 1];
    __half2 h0 = __floats2half2_rn(a.x, a.y);
    __half2 h1 = __floats2half2_rn(a.z, a.w);
    __half2 h2 = __floats2half2_rn(b.x, b.y);
    __half2 h3 = __floats2half2_rn(b.z, b.w);
    uint4 o;
    o.x = *reinterpret_cast<uint32_t*>(&h0);
    o.y = *reinterpret_cast<uint32_t*>(&h1);
    o.z = *reinterpret_cast<uint32_t*>(&h2);
    o.w = *reinterpret_cast<uint32_t*>(&h3);
    xh[t] = o;
}

// ---------------- HMMA GEMM: out[M,N] = xh[M,K] @ wdq[N,K]^T + bias ----------------
__global__ void __launch_bounds__(256, 1) gemm_kernel(
    const __grid_constant__ CUtensorMap tm_x,
    const __grid_constant__ CUtensorMap tm_w,
    const float* __restrict__ bias,
    float* __restrict__ out)
{
    extern __shared__ char smem_raw[];
    const uint32_t sb = (smem_u32(smem_raw) + 1023u) & ~1023u;   // 1KB align for SW128

    const int tid  = threadIdx.x;
    const int wid  = tid >> 5;
    const int lane = tid & 31;
    const int m0 = (int)(blockIdx.x >> 4) * TILE_M;              // 64 m-tiles
    const int n0 = (int)(blockIdx.x & 15) * TILE_N;              // 16 n-tiles

    if (tid == 0) {
        #pragma unroll
        for (int s = 0; s < STAGES; s++) {
            MBAR_INIT(sb + OFF_FULL(s), 1);
            MBAR_INIT(sb + OFF_EMPTY(s), 8);     // 8 warps arrive
        }
    }
    __syncthreads();

    // prologue: fill all stages
    if (tid == 0) {
        #pragma unroll
        for (int s = 0; s < STAGES; s++) {
            MBAR_EXPECT_TX(sb + OFF_FULL(s), STAGE_BYTES);
            uint32_t st = sb + SMEM_CTRL + s * STAGE_BYTES;
            tma2d(st,           &tm_x, s * KCHUNK, m0, sb + OFF_FULL(s));
            tma2d(st + A_BYTES, &tm_w, s * KCHUNK, n0, sb + OFF_FULL(s));
        }
    }

    // per-thread ldmatrix addressing (SW128: physical = logical ^ ((row&7)<<4))
    const int sel = lane >> 3, l7 = lane & 7;
    const uint32_t xm = (uint32_t)l7 << 4;
    const int mwarp = (wid & 1) * 64;
    const int nwarp = (wid >> 1) * 64;
    const int rA = ((sel & 1) << 3) + l7;            // A: sel0,2 -> rows 0-7; sel1,3 -> rows 8-15
    const uint32_t kbA = (uint32_t)(sel >> 1) << 4;  // A: sel2,3 -> k+8 (16B)
    const int rB = (((sel >> 1) & 1) << 3) + l7;     // B: sel2,3 -> n+8
    const uint32_t kbB = (uint32_t)(sel & 1) << 4;   // B: sel1,3 -> k+8
    uint32_t rowA[4], rowB[4];
    #pragma unroll
    for (int f = 0; f < 4; f++) rowA[f] = (uint32_t)(mwarp + f * 16 + rA) * 128u;
    #pragma unroll
    for (int g = 0; g < 4; g++) rowB[g] = (uint32_t)(nwarp + g * 16 + rB) * 128u + (uint32_t)A_BYTES;

    float d[4][8][4] = {};

    int s = 0;
    uint32_t phf = 0, phe = 0;
    #pragma unroll 1
    for (int i = 0; i < NCHUNKS; i++) {
        MBAR_WAIT(sb + OFF_FULL(s), phf);
        const uint32_t st = sb + SMEM_CTRL + s * STAGE_BYTES;

        #pragma unroll
        for (int kk = 0; kk < KCHUNK / 16; kk++) {
            const uint32_t kb = (uint32_t)kk << 5;          // kk*32 bytes
            uint32_t bb[4][4], aa[4][4];
            #pragma unroll
            for (int g = 0; g < 4; g++) ldsm4(bb[g], st + rowB[g] + ((kb + kbB) ^ xm));
            #pragma unroll
            for (int f = 0; f < 4; f++) ldsm4(aa[f], st + rowA[f] + ((kb + kbA) ^ xm));
            #pragma unroll
            for (int f = 0; f < 4; f++)
                #pragma unroll
                for (int g = 0; g < 4; g++) {
                    mma16816(d[f][2 * g],     aa[f], &bb[g][0]);
                    mma16816(d[f][2 * g + 1], aa[f], &bb[g][2]);
                }
        }

        __syncwarp();
        if (lane == 0) MBAR_ARRIVE(sb + OFF_EMPTY(s));

        if (tid == 0 && i + STAGES < NCHUNKS) {
            MBAR_WAIT(sb + OFF_EMPTY(s), phe);
            MBAR_EXPECT_TX(sb + OFF_FULL(s), STAGE_BYTES);
            const int c = (i + STAGES) * KCHUNK;
            tma2d(st,           &tm_x, c, m0, sb + OFF_FULL(s));
            tma2d(st + A_BYTES, &tm_w, c, n0, sb + OFF_FULL(s));
        }
        if (++s == STAGES) { s = 0; phf ^= 1; phe ^= 1; }
    }

    // ---- epilogue: registers -> gmem, add bias ----
    const int g2 = lane >> 2, tg = lane & 3;
    float bv0[8], bv1[8];
    #pragma unroll
    for (int nf = 0; nf < 8; nf++) {
        const int n = n0 + nwarp + nf * 8 + tg * 2;
        bv0[nf] = bias[n];
        bv1[nf] = bias[n + 1];
    }
    #pragma unroll
    for (int f = 0; f < 4; f++) {
        const int mrow = m0 + mwarp + f * 16 + g2;
        #pragma unroll
        for (int nf = 0; nf < 8; nf++) {
            const int n = n0 + nwarp + nf * 8 + tg * 2;
            float2 v0 = make_float2(d[f][nf][0] + bv0[nf], d[f][nf][1] + bv1[nf]);
            float2 v1 = make_float2(d[f][nf][2] + bv0[nf], d[f][nf][3] + bv1[nf]);
            *reinterpret_cast<float2*>(&out[(size_t)mrow * N_DIM + n]) = v0;
            *reinterpret_cast<float2*>(&out[(size_t)(mrow + 8) * N_DIM + n]) = v1;
        }
    }
}

// ---------------- host ----------------
typedef CUresult (*PFN_EncodeTiled)(
    CUtensorMap*, CUtensorMapDataType, cuuint32_t, void*,
    const cuuint64_t*, const cuuint64_t*, const cuuint32_t*, const cuuint32_t*,
    CUtensorMapInterleave, CUtensorMapSwizzle, CUtensorMapL2promotion, CUtensorMapFloatOOBfill);

static void make_map_2d(PFN_EncodeTiled fn, CUtensorMap* m, void* ptr,
                        uint64_t rows, uint32_t boxRows) {
    cuuint64_t dims[2]    = {(cuuint64_t)K_DIM, (cuuint64_t)rows};
    cuuint64_t strides[1] = {(cuuint64_t)K_DIM * 2};
    cuuint32_t box[2]     = {(cuuint32_t)KCHUNK, boxRows};   // 64 fp16 = 128B (SW128 limit)
    cuuint32_t es[2]      = {1, 1};
    fn(m, CU_TENSOR_MAP_DATA_TYPE_FLOAT16, 2, ptr, dims, strides, box, es,
       CU_TENSOR_MAP_INTERLEAVE_NONE, CU_TENSOR_MAP_SWIZZLE_128B,
       CU_TENSOR_MAP_L2_PROMOTION_L2_128B, CU_TENSOR_MAP_FLOAT_OOB_FILL_NONE);
}

extern "C" void kernel_launch(void* const* d_in, const int* in_sizes, int n_in,
                              void* d_out, int out_size) {
    const float* x    = (const float*)d_in[0];
    const float* w    = (const float*)d_in[1];
    const float* bias = (const float*)d_in[2];
    float* out = (float*)d_out;

    void *p_wdq, *p_xh;
    cudaGetSymbolAddress(&p_wdq, g_wdq);
    cudaGetSymbolAddress(&p_xh, g_xh);

    // 1) quantize weight -> exact fp16 dequant plane (8 elems/thread)
    quant_kernel<<<(N_DIM * K_DIM / 8) / 256, 256>>>((const float4*)w, (uint4*)p_wdq);

    // 2) x -> fp16
    convert_kernel<<<(M_DIM * K_DIM / 8) / 256, 256>>>((const float4*)x, (uint4*)p_xh);

    // 3) tensor maps
    PFN_EncodeTiled fn = nullptr;
    cudaDriverEntryPointQueryResult qres;
    cudaGetDriverEntryPointByVersion("cuTensorMapEncodeTiled", (void**)&fn, 12000,
                                     cudaEnableDefault, &qres);
    if (!fn) return;

    CUtensorMap tm_x, tm_w;
    make_map_2d(fn, &tm_x, p_xh,  M_DIM, TILE_M);
    make_map_2d(fn, &tm_w, p_wdq, N_DIM, TILE_N);

    cudaFuncSetAttribute(gemm_kernel, cudaFuncAttributeMaxDynamicSharedMemorySize, SMEM_REQ);
    gemm_kernel<<<(M_DIM / TILE_M) * (N_DIM / TILE_N), 256, SMEM_REQ>>>(
        tm_x, tm_w, bias, out);
}

// round 4
// speedup vs baseline: 2.1873x; 1.0036x over previous
#include <cuda_runtime.h>
#include <cuda.h>
#include <cuda_fp16.h>
#include <cuda_fp8.h>
#include <cstdint>

#define DI __device__ __forceinline__

// ---------------- problem dims ----------------
static constexpr int M_DIM = 8192;
static constexpr int N_DIM = 4096;
static constexpr int K_DIM = 4096;

// ---------------- GEMM tiling ----------------
static constexpr int TILE_M = 128;
static constexpr int TILE_N = 256;
static constexpr int KCHUNK = 64;                      // fp16 elems per k-chunk (128B rows, SW128)
static constexpr int NCHUNKS = K_DIM / KCHUNK;         // 64
static constexpr int STAGES  = 4;
static constexpr int A_BYTES = TILE_M * KCHUNK * 2;    // 16 KB
static constexpr int B_BYTES = TILE_N * KCHUNK * 2;    // 32 KB
static constexpr int STAGE_BYTES = A_BYTES + B_BYTES;  // 48 KB
static constexpr int SMEM_CTRL  = 1024;
static constexpr int SMEM_REQ   = SMEM_CTRL + STAGES * STAGE_BYTES + 1024;  // ~199 KB

#define OFF_FULL(s)  ((s)*16)
#define OFF_EMPTY(s) ((s)*16 + 8)

// ---------------- device scratch (no cudaMalloc allowed) ----------------
__device__ __align__(1024) __half g_wdq[(size_t)N_DIM * K_DIM];   // 32 MB
__device__ __align__(1024) __half g_xh[(size_t)M_DIM * K_DIM];    // 64 MB

// ---------------- PTX helpers ----------------
DI uint32_t smem_u32(const void* p) {
    uint32_t a;
    asm("{ .reg .u64 t; cvta.to.shared.u64 t, %1; cvt.u32.u64 %0, t; }" : "=r"(a) : "l"(p));
    return a;
}

#define MBAR_INIT(mbar, cnt) \
    asm volatile("mbarrier.init.shared.b64 [%0], %1;" :: "r"((uint32_t)(mbar)), "r"((uint32_t)(cnt)) : "memory")
#define MBAR_EXPECT_TX(mbar, bytes) \
    asm volatile("mbarrier.arrive.expect_tx.shared.b64 _, [%0], %1;" \
                 :: "r"((uint32_t)(mbar)), "r"((uint32_t)(bytes)) : "memory")
#define MBAR_ARRIVE(mbar) \
    asm volatile("mbarrier.arrive.shared.b64 _, [%0];" :: "r"((uint32_t)(mbar)) : "memory")
#define MBAR_WAIT(mbar, ph) do { \
    asm volatile("{\n\t.reg .pred P1;\n\t" \
        "WAIT_%=:\n\t" \
        "mbarrier.try_wait.parity.acquire.cta.shared::cta.b64 P1, [%0], %1, 0x989680;\n\t" \
        "@P1 bra.uni DONE_%=;\n\t" \
        "bra.uni WAIT_%=;\n\t" \
        "DONE_%=:\n\t}" :: "r"((uint32_t)(mbar)), "r"((uint32_t)(ph)) : "memory"); \
} while (0)

DI void tma2d(uint32_t dst, const CUtensorMap* map, int cx, int cy, uint32_t mbar) {
    asm volatile(
        "cp.async.bulk.tensor.2d.shared::cta.global.tile.mbarrier::complete_tx::bytes "
        "[%0], [%1, {%2, %3}], [%4];"
        :: "r"(dst), "l"(map), "r"(cx), "r"(cy), "r"(mbar) : "memory");
}

DI void ldsm4(uint32_t* r, uint32_t addr) {
    asm volatile("ldmatrix.sync.aligned.m8n8.x4.shared.b16 {%0,%1,%2,%3}, [%4];"
                 : "=r"(r[0]), "=r"(r[1]), "=r"(r[2]), "=r"(r[3]) : "r"(addr));
}

DI void mma16816(float* d, const uint32_t* a, const uint32_t* b) {
    asm volatile(
        "mma.sync.aligned.m16n8k16.row.col.f32.f16.f16.f32 "
        "{%0,%1,%2,%3}, {%4,%5,%6,%7}, {%8,%9}, {%0,%1,%2,%3};"
        : "+f"(d[0]), "+f"(d[1]), "+f"(d[2]), "+f"(d[3])
        : "r"(a[0]), "r"(a[1]), "r"(a[2]), "r"(a[3]), "r"(b[0]), "r"(b[1]));
}

// ---------------- codebook round (ties toward lower value, matching argmin) ----------------
DI float cb_round(float a) {
    // a >= 0 (possibly > 6; then -> 6, which equals clip-then-round)
    float q1 = ceilf(__fmaf_rn(2.0f, a, -0.5f)) * 0.5f;   // a in [0,2]: half-steps, tie-down
    float q2 = ceilf(a - 0.5f);                            // a in (2,4]: unit steps, tie-down
    float q3 = (a <= 5.0f) ? 4.0f : 6.0f;                  // a in (4,inf): 4 or 6, tie at 5 -> 4
    return (a <= 2.0f) ? q1 : ((a <= 4.0f) ? q2 : q3);
}

static constexpr int QUANT_BLOCKS = (N_DIM * K_DIM / 8) / 256;     //  8192
static constexpr int CONV_BLOCKS  = (M_DIM * K_DIM / 8) / 256;     // 16384

// ---------------- fused prep: W quantize (blocks 0..8191) + x->fp16 (rest) ----------------
__global__ void __launch_bounds__(256) prep_kernel(const float4* __restrict__ w4,
                                                   uint4* __restrict__ wdq,
                                                   const float4* __restrict__ x4,
                                                   uint4* __restrict__ xh) {
    if (blockIdx.x >= QUANT_BLOCKS) {
        // -------- x -> fp16 (memory-bound; fills around quant compute) --------
        const int t = (blockIdx.x - QUANT_BLOCKS) * 256 + threadIdx.x;
        float4 a = x4[2 * t], b = x4[2 * t + 1];
        __half2 h0 = __floats2half2_rn(a.x, a.y);
        __half2 h1 = __floats2half2_rn(a.z, a.w);
        __half2 h2 = __floats2half2_rn(b.x, b.y);
        __half2 h3 = __floats2half2_rn(b.z, b.w);
        uint4 o;
        o.x = *reinterpret_cast<uint32_t*>(&h0);
        o.y = *reinterpret_cast<uint32_t*>(&h1);
        o.z = *reinterpret_cast<uint32_t*>(&h2);
        o.w = *reinterpret_cast<uint32_t*>(&h3);
        xh[t] = o;
        return;
    }

    // -------- NVFP4 quantizer: 4 threads per 32-block, 8 elems/thread --------
    const int t = blockIdx.x * 256 + threadIdx.x;     // one thread = 8 elements
    const float4 va = w4[2 * t];
    const float4 vb = w4[2 * t + 1];
    float v[8]  = {va.x, va.y, va.z, va.w, vb.x, vb.y, vb.z, vb.w};
    float av[8];
    #pragma unroll
    for (int j = 0; j < 8; j++) av[j] = fabsf(v[j]);

    // block max over 32 elements = 4 threads (quad butterfly)
    float mx = av[0];
    #pragma unroll
    for (int j = 1; j < 8; j++) mx = fmaxf(mx, av[j]);
    mx = fmaxf(mx, __shfl_xor_sync(0xffffffffu, mx, 1));
    mx = fmaxf(mx, __shfl_xor_sync(0xffffffffu, mx, 2));
    const float bm = fmaxf(mx, 1e-12f);
    const float rinv = 1.0f / bm;                      // single division per thread

    // u[j]: magnitudes normalized to [0,1]; per-ratio scale is a compile-time const
    float u[8];
    #pragma unroll
    for (int j = 0; j < 8; j++) u[j] = av[j] * rinv;

    float best_mse = __int_as_float(0x7f800000);       // +inf
    float best_c = 0.0f, best_r = 0.0f;

    #pragma unroll
    for (int ti = 0; ti < 10; ti++) {
        const double rd = (ti == 9) ? 1.0 : (0.7 + (double)ti * (0.3 / 9.0));
        const float rf = (float)rd;                    // ratio (compile-time)
        const float c  = 6.0f / rf;                    // u -> codebook domain

        float e = 0.0f;
        #pragma unroll
        for (int j = 0; j < 8; j++) {
            float s = u[j] * c;                        // scaled magnitude
            float q = cb_round(s);
            float d = s - q;
            e = __fmaf_rn(d, d, e);
        }
        e += __shfl_xor_sync(0xffffffffu, e, 1);
        e += __shfl_xor_sync(0xffffffffu, e, 2);
        // domain factor (s6^2) folded: compare e * rf^2 (bm^2 common to all)
        float em = e * (rf * rf);
        if (em < best_mse) { best_mse = em; best_c = c; best_r = rf; }
    }

    // ue4m3 scale round-trip (matches reference astype(float8_e4m3fn))
    const float sf = (float)__nv_fp8_e4m3(bm * (best_r * (1.0f / 6.0f)));

    __half h[8];
    #pragma unroll
    for (int j = 0; j < 8; j++) {
        float q = copysignf(cb_round(u[j] * best_c), v[j]);
        h[j] = __float2half_rn(q * sf);                // <=5 significand bits: exact in fp16
    }
    uint4 o;
    o.x = *reinterpret_cast<uint32_t*>(&h[0]);
    o.y = *reinterpret_cast<uint32_t*>(&h[2]);
    o.z = *reinterpret_cast<uint32_t*>(&h[4]);
    o.w = *reinterpret_cast<uint32_t*>(&h[6]);
    wdq[t] = o;
}

// ---------------- HMMA GEMM: out[M,N] = xh[M,K] @ wdq[N,K]^T + bias ----------------
__global__ void __launch_bounds__(256, 1) gemm_kernel(
    const __grid_constant__ CUtensorMap tm_x,
    const __grid_constant__ CUtensorMap tm_w,
    const float* __restrict__ bias,
    float* __restrict__ out)
{
    extern __shared__ char smem_raw[];
    const uint32_t sb = (smem_u32(smem_raw) + 1023u) & ~1023u;   // 1KB align for SW128

    const int tid  = threadIdx.x;
    const int wid  = tid >> 5;
    const int lane = tid & 31;
    const int m0 = (int)(blockIdx.x >> 4) * TILE_M;              // 64 m-tiles
    const int n0 = (int)(blockIdx.x & 15) * TILE_N;              // 16 n-tiles

    if (tid == 0) {
        #pragma unroll
        for (int s = 0; s < STAGES; s++) {
            MBAR_INIT(sb + OFF_FULL(s), 1);
            MBAR_INIT(sb + OFF_EMPTY(s), 8);     // 8 warps arrive
        }
    }
    __syncthreads();

    // prologue: fill all stages
    if (tid == 0) {
        #pragma unroll
        for (int s = 0; s < STAGES; s++) {
            MBAR_EXPECT_TX(sb + OFF_FULL(s), STAGE_BYTES);
            uint32_t st = sb + SMEM_CTRL + s * STAGE_BYTES;
            tma2d(st,           &tm_x, s * KCHUNK, m0, sb + OFF_FULL(s));
            tma2d(st + A_BYTES, &tm_w, s * KCHUNK, n0, sb + OFF_FULL(s));
        }
    }

    // per-thread ldmatrix addressing (SW128: physical = logical ^ ((row&7)<<4))
    const int sel = lane >> 3, l7 = lane & 7;
    const uint32_t xm = (uint32_t)l7 << 4;
    const int mwarp = (wid & 1) * 64;
    const int nwarp = (wid >> 1) * 64;
    const int rA = ((sel & 1) << 3) + l7;            // A: sel0,2 -> rows 0-7; sel1,3 -> rows 8-15
    const uint32_t kbA = (uint32_t)(sel >> 1) << 4;  // A: sel2,3 -> k+8 (16B)
    const int rB = (((sel >> 1) & 1) << 3) + l7;     // B: sel2,3 -> n+8
    const uint32_t kbB = (uint32_t)(sel & 1) << 4;   // B: sel1,3 -> k+8
    uint32_t rowA[4], rowB[4];
    #pragma unroll
    for (int f = 0; f < 4; f++) rowA[f] = (uint32_t)(mwarp + f * 16 + rA) * 128u;
    #pragma unroll
    for (int g = 0; g < 4; g++) rowB[g] = (uint32_t)(nwarp + g * 16 + rB) * 128u + (uint32_t)A_BYTES;

    float d[4][8][4] = {};

    int s = 0;
    uint32_t phf = 0, phe = 0;
    #pragma unroll 1
    for (int i = 0; i < NCHUNKS; i++) {
        MBAR_WAIT(sb + OFF_FULL(s), phf);
        const uint32_t st = sb + SMEM_CTRL + s * STAGE_BYTES;

        #pragma unroll
        for (int kk = 0; kk < KCHUNK / 16; kk++) {
            const uint32_t kb = (uint32_t)kk << 5;          // kk*32 bytes
            uint32_t bb[4][4], aa[4][4];
            #pragma unroll
            for (int g = 0; g < 4; g++) ldsm4(bb[g], st + rowB[g] + ((kb + kbB) ^ xm));
            #pragma unroll
            for (int f = 0; f < 4; f++) ldsm4(aa[f], st + rowA[f] + ((kb + kbA) ^ xm));
            #pragma unroll
            for (int f = 0; f < 4; f++)
                #pragma unroll
                for (int g = 0; g < 4; g++) {
                    mma16816(d[f][2 * g],     aa[f], &bb[g][0]);
                    mma16816(d[f][2 * g + 1], aa[f], &bb[g][2]);
                }
        }

        __syncwarp();
        if (lane == 0) MBAR_ARRIVE(sb + OFF_EMPTY(s));

        if (tid == 0 && i + STAGES < NCHUNKS) {
            MBAR_WAIT(sb + OFF_EMPTY(s), phe);
            MBAR_EXPECT_TX(sb + OFF_FULL(s), STAGE_BYTES);
            const int c = (i + STAGES) * KCHUNK;
            tma2d(st,           &tm_x, c, m0, sb + OFF_FULL(s));
            tma2d(st + A_BYTES, &tm_w, c, n0, sb + OFF_FULL(s));
        }
        if (++s == STAGES) { s = 0; phf ^= 1; phe ^= 1; }
    }

    // ---- epilogue: registers -> gmem, add bias ----
    const int g2 = lane >> 2, tg = lane & 3;
    float bv0[8], bv1[8];
    #pragma unroll
    for (int nf = 0; nf < 8; nf++) {
        const int n = n0 + nwarp + nf * 8 + tg * 2;
        bv0[nf] = bias[n];
        bv1[nf] = bias[n + 1];
    }
    #pragma unroll
    for (int f = 0; f < 4; f++) {
        const int mrow = m0 + mwarp + f * 16 + g2;
        #pragma unroll
        for (int nf = 0; nf < 8; nf++) {
            const int n = n0 + nwarp + nf * 8 + tg * 2;
            float2 v0 = make_float2(d[f][nf][0] + bv0[nf], d[f][nf][1] + bv1[nf]);
            float2 v1 = make_float2(d[f][nf][2] + bv0[nf], d[f][nf][3] + bv1[nf]);
            *reinterpret_cast<float2*>(&out[(size_t)mrow * N_DIM + n]) = v0;
            *reinterpret_cast<float2*>(&out[(size_t)(mrow + 8) * N_DIM + n]) = v1;
        }
    }
}

// ---------------- host ----------------
typedef CUresult (*PFN_EncodeTiled)(
    CUtensorMap*, CUtensorMapDataType, cuuint32_t, void*,
    const cuuint64_t*, const cuuint64_t*, const cuuint32_t*, const cuuint32_t*,
    CUtensorMapInterleave, CUtensorMapSwizzle, CUtensorMapL2promotion, CUtensorMapFloatOOBfill);

static void make_map_2d(PFN_EncodeTiled fn, CUtensorMap* m, void* ptr,
                        uint64_t rows, uint32_t boxRows) {
    cuuint64_t dims[2]    = {(cuuint64_t)K_DIM, (cuuint64_t)rows};
    cuuint64_t strides[1] = {(cuuint64_t)K_DIM * 2};
    cuuint32_t box[2]     = {(cuuint32_t)KCHUNK, boxRows};   // 64 fp16 = 128B (SW128 limit)
    cuuint32_t es[2]      = {1, 1};
    fn(m, CU_TENSOR_MAP_DATA_TYPE_FLOAT16, 2, ptr, dims, strides, box, es,
       CU_TENSOR_MAP_INTERLEAVE_NONE, CU_TENSOR_MAP_SWIZZLE_128B,
       CU_TENSOR_MAP_L2_PROMOTION_L2_128B, CU_TENSOR_MAP_FLOAT_OOB_FILL_NONE);
}

extern "C" void kernel_launch(void* const* d_in, const int* in_sizes, int n_in,
                              void* d_out, int out_size) {
    const float* x    = (const float*)d_in[0];
    const float* w    = (const float*)d_in[1];
    const float* bias = (const float*)d_in[2];
    float* out = (float*)d_out;

    void *p_wdq, *p_xh;
    cudaGetSymbolAddress(&p_wdq, g_wdq);
    cudaGetSymbolAddress(&p_xh, g_xh);

    // 1) fused: quantize W -> exact fp16 plane, convert x -> fp16
    prep_kernel<<<QUANT_BLOCKS + CONV_BLOCKS, 256>>>(
        (const float4*)w, (uint4*)p_wdq, (const float4*)x, (uint4*)p_xh);

    // 2) tensor maps
    PFN_EncodeTiled fn = nullptr;
    cudaDriverEntryPointQueryResult qres;
    cudaGetDriverEntryPointByVersion("cuTensorMapEncodeTiled", (void**)&fn, 12000,
                                     cudaEnableDefault, &qres);
    if (!fn) return;

    CUtensorMap tm_x, tm_w;
    make_map_2d(fn, &tm_x, p_xh,  M_DIM, TILE_M);
    make_map_2d(fn, &tm_w, p_wdq, N_DIM, TILE_N);

    cudaFuncSetAttribute(gemm_kernel, cudaFuncAttributeMaxDynamicSharedMemorySize, SMEM_REQ);
    gemm_kernel<<<(M_DIM / TILE_M) * (N_DIM / TILE_N), 256, SMEM_REQ>>>(
        tm_x, tm_w, bias, out);
}

// round 6
// speedup vs baseline: 2.2116x; 1.0111x over previous
#include <cuda_runtime.h>
#include <cuda.h>
#include <cuda_fp16.h>
#include <cuda_fp8.h>
#include <cstdint>

#define DI __device__ __forceinline__

// ---------------- problem dims ----------------
static constexpr int M_DIM = 8192;
static constexpr int N_DIM = 4096;
static constexpr int K_DIM = 4096;

// ---------------- GEMM tiling ----------------
static constexpr int TILE_M = 128;
static constexpr int TILE_N = 256;
static constexpr int KCHUNK = 64;                      // fp16 elems per k-chunk (128B rows, SW128)
static constexpr int NCHUNKS = K_DIM / KCHUNK;         // 64
static constexpr int STAGES  = 4;
static constexpr int NTILES  = (M_DIM / TILE_M) * (N_DIM / TILE_N);  // 1024
static constexpr int GRID_SM = 148;                    // persistent CTAs (1/SM)
static constexpr int A_BYTES = TILE_M * KCHUNK * 2;    // 16 KB
static constexpr int B_BYTES = TILE_N * KCHUNK * 2;    // 32 KB
static constexpr int STAGE_BYTES = A_BYTES + B_BYTES;  // 48 KB
static constexpr int SMEM_CTRL  = 1024;
static constexpr int SMEM_REQ   = SMEM_CTRL + STAGES * STAGE_BYTES + 1024;  // ~199 KB

#define OFF_FULL(s)  ((s)*16)
#define OFF_EMPTY(s) ((s)*16 + 8)

// ---------------- device scratch (no cudaMalloc allowed) ----------------
__device__ __align__(1024) __half g_wdq[(size_t)N_DIM * K_DIM];   // 32 MB
__device__ __align__(1024) __half g_xh[(size_t)M_DIM * K_DIM];    // 64 MB

// ---------------- PTX helpers ----------------
DI uint32_t smem_u32(const void* p) {
    uint32_t a;
    asm("{ .reg .u64 t; cvta.to.shared.u64 t, %1; cvt.u32.u64 %0, t; }" : "=r"(a) : "l"(p));
    return a;
}

#define MBAR_INIT(mbar, cnt) \
    asm volatile("mbarrier.init.shared.b64 [%0], %1;" :: "r"((uint32_t)(mbar)), "r"((uint32_t)(cnt)) : "memory")
#define MBAR_EXPECT_TX(mbar, bytes) \
    asm volatile("mbarrier.arrive.expect_tx.shared.b64 _, [%0], %1;" \
                 :: "r"((uint32_t)(mbar)), "r"((uint32_t)(bytes)) : "memory")
#define MBAR_ARRIVE(mbar) \
    asm volatile("mbarrier.arrive.shared.b64 _, [%0];" :: "r"((uint32_t)(mbar)) : "memory")
#define MBAR_WAIT(mbar, ph) do { \
    asm volatile("{\n\t.reg .pred P1;\n\t" \
        "WAIT_%=:\n\t" \
        "mbarrier.try_wait.parity.acquire.cta.shared::cta.b64 P1, [%0], %1, 0x989680;\n\t" \
        "@P1 bra.uni DONE_%=;\n\t" \
        "bra.uni WAIT_%=;\n\t" \
        "DONE_%=:\n\t}" :: "r"((uint32_t)(mbar)), "r"((uint32_t)(ph)) : "memory"); \
} while (0)

DI void tma2d(uint32_t dst, const CUtensorMap* map, int cx, int cy, uint32_t mbar) {
    asm volatile(
        "cp.async.bulk.tensor.2d.shared::cta.global.tile.mbarrier::complete_tx::bytes "
        "[%0], [%1, {%2, %3}], [%4];"
        :: "r"(dst), "l"(map), "r"(cx), "r"(cy), "r"(mbar) : "memory");
}

DI void ldsm4(uint32_t* r, uint32_t addr) {
    asm volatile("ldmatrix.sync.aligned.m8n8.x4.shared.b16 {%0,%1,%2,%3}, [%4];"
                 : "=r"(r[0]), "=r"(r[1]), "=r"(r[2]), "=r"(r[3]) : "r"(addr));
}

DI void mma16816(float* d, const uint32_t* a, const uint32_t* b) {
    asm volatile(
        "mma.sync.aligned.m16n8k16.row.col.f32.f16.f16.f32 "
        "{%0,%1,%2,%3}, {%4,%5,%6,%7}, {%8,%9}, {%0,%1,%2,%3};"
        : "+f"(d[0]), "+f"(d[1]), "+f"(d[2]), "+f"(d[3])
        : "r"(a[0]), "r"(a[1]), "r"(a[2]), "r"(a[3]), "r"(b[0]), "r"(b[1]));
}

// ---------------- codebook round (ties toward lower value, matching argmin) ----------------
DI float cb_round(float a) {
    // a >= 0 (possibly > 6; then -> 6, which equals clip-then-round)
    float q1 = ceilf(__fmaf_rn(2.0f, a, -0.5f)) * 0.5f;   // a in [0,2]: half-steps, tie-down
    float q2 = ceilf(a - 0.5f);                            // a in (2,4]: unit steps, tie-down
    float q3 = (a <= 5.0f) ? 4.0f : 6.0f;                  // a in (4,inf): 4 or 6, tie at 5 -> 4
    return (a <= 2.0f) ? q1 : ((a <= 4.0f) ? q2 : q3);
}

static constexpr int QUANT_BLOCKS = (N_DIM * K_DIM / 8) / 256;     //  8192
static constexpr int CONV_BLOCKS  = (M_DIM * K_DIM / 8) / 256;     // 16384

// ---------------- fused prep: W quantize (blocks 0..8191) + x->fp16 (rest) ----------------
__global__ void __launch_bounds__(256) prep_kernel(const float4* __restrict__ w4,
                                                   uint4* __restrict__ wdq,
                                                   const float4* __restrict__ x4,
                                                   uint4* __restrict__ xh) {
    if (blockIdx.x >= QUANT_BLOCKS) {
        // -------- x -> fp16 (memory-bound; fills around quant compute) --------
        const int t = (blockIdx.x - QUANT_BLOCKS) * 256 + threadIdx.x;
        float4 a = x4[2 * t], b = x4[2 * t + 1];
        __half2 h0 = __floats2half2_rn(a.x, a.y);
        __half2 h1 = __floats2half2_rn(a.z, a.w);
        __half2 h2 = __floats2half2_rn(b.x, b.y);
        __half2 h3 = __floats2half2_rn(b.z, b.w);
        uint4 o;
        o.x = *reinterpret_cast<uint32_t*>(&h0);
        o.y = *reinterpret_cast<uint32_t*>(&h1);
        o.z = *reinterpret_cast<uint32_t*>(&h2);
        o.w = *reinterpret_cast<uint32_t*>(&h3);
        xh[t] = o;
        return;
    }

    // -------- NVFP4 quantizer: 4 threads per 32-block, 8 elems/thread --------
    const int t = blockIdx.x * 256 + threadIdx.x;     // one thread = 8 elements
    const float4 va = w4[2 * t];
    const float4 vb = w4[2 * t + 1];
    float v[8]  = {va.x, va.y, va.z, va.w, vb.x, vb.y, vb.z, vb.w};
    float av[8];
    #pragma unroll
    for (int j = 0; j < 8; j++) av[j] = fabsf(v[j]);

    // block max over 32 elements = 4 threads (quad butterfly)
    float mx = av[0];
    #pragma unroll
    for (int j = 1; j < 8; j++) mx = fmaxf(mx, av[j]);
    mx = fmaxf(mx, __shfl_xor_sync(0xffffffffu, mx, 1));
    mx = fmaxf(mx, __shfl_xor_sync(0xffffffffu, mx, 2));
    const float bm = fmaxf(mx, 1e-12f);
    const float rinv = 1.0f / bm;                      // single division per thread

    // u[j]: magnitudes normalized to [0,1]; per-ratio scale is a compile-time const
    float u[8];
    #pragma unroll
    for (int j = 0; j < 8; j++) u[j] = av[j] * rinv;

    float best_mse = __int_as_float(0x7f800000);       // +inf
    float best_c = 0.0f, best_r = 0.0f;

    #pragma unroll
    for (int ti = 0; ti < 10; ti++) {
        const double rd = (ti == 9) ? 1.0 : (0.7 + (double)ti * (0.3 / 9.0));
        const float rf = (float)rd;                    // ratio (compile-time)
        const float c  = 6.0f / rf;                    // u -> codebook domain

        float e = 0.0f;
        #pragma unroll
        for (int j = 0; j < 8; j++) {
            float s = u[j] * c;                        // scaled magnitude
            float q = cb_round(s);
            float d = s - q;
            e = __fmaf_rn(d, d, e);
        }
        e += __shfl_xor_sync(0xffffffffu, e, 1);
        e += __shfl_xor_sync(0xffffffffu, e, 2);
        // domain factor (s6^2) folded: compare e * rf^2 (bm^2 common to all)
        float em = e * (rf * rf);
        if (em < best_mse) { best_mse = em; best_c = c; best_r = rf; }
    }

    // ue4m3 scale round-trip (matches reference astype(float8_e4m3fn))
    const float sf = (float)__nv_fp8_e4m3(bm * (best_r * (1.0f / 6.0f)));

    __half h[8];
    #pragma unroll
    for (int j = 0; j < 8; j++) {
        float q = copysignf(cb_round(u[j] * best_c), v[j]);
        h[j] = __float2half_rn(q * sf);                // <=5 significand bits: exact in fp16
    }
    uint4 o;
    o.x = *reinterpret_cast<uint32_t*>(&h[0]);
    o.y = *reinterpret_cast<uint32_t*>(&h[2]);
    o.z = *reinterpret_cast<uint32_t*>(&h[4]);
    o.w = *reinterpret_cast<uint32_t*>(&h[6]);
    wdq[t] = o;
}

// ---------------- persistent HMMA GEMM: out[M,N] = xh[M,K] @ wdq[N,K]^T + bias ----------------
// 148 CTAs, each loops over ~7 tiles; the TMA ring runs continuously across tile
// boundaries so next-tile prefetch overlaps the current tile's epilogue.
__global__ void __launch_bounds__(256, 1) gemm_kernel(
    const __grid_constant__ CUtensorMap tm_x,
    const __grid_constant__ CUtensorMap tm_w,
    const float* __restrict__ bias,
    float* __restrict__ out)
{
    extern __shared__ char smem_raw[];
    const uint32_t sb = (smem_u32(smem_raw) + 1023u) & ~1023u;   // 1KB align for SW128

    const int tid  = threadIdx.x;
    const int wid  = tid >> 5;
    const int lane = tid & 31;
    const int bid  = blockIdx.x;
    const int gsz  = gridDim.x;

    const int ntiles = (NTILES - bid + gsz - 1) / gsz;           // 6 or 7
    const uint32_t totalChunks = (uint32_t)ntiles * NCHUNKS;

    if (tid == 0) {
        #pragma unroll
        for (int s = 0; s < STAGES; s++) {
            MBAR_INIT(sb + OFF_FULL(s), 1);
            MBAR_INIT(sb + OFF_EMPTY(s), 8);     // 8 warps arrive
        }
    }
    __syncthreads();

    // prologue: fill the first STAGES chunks of my first tile
    if (tid == 0) {
        const int t0 = bid;
        const int pm0 = (t0 >> 4) * TILE_M;
        const int pn0 = (t0 & 15) * TILE_N;
        #pragma unroll
        for (int f = 0; f < STAGES; f++) {
            MBAR_EXPECT_TX(sb + OFF_FULL(f), STAGE_BYTES);
            uint32_t st = sb + SMEM_CTRL + f * STAGE_BYTES;
            tma2d(st,           &tm_x, f * KCHUNK, pm0, sb + OFF_FULL(f));
            tma2d(st + A_BYTES, &tm_w, f * KCHUNK, pn0, sb + OFF_FULL(f));
        }
    }

    // per-thread ldmatrix addressing (SW128: physical = logical ^ ((row&7)<<4))
    const int sel = lane >> 3, l7 = lane & 7;
    const uint32_t xm = (uint32_t)l7 << 4;
    const int mwarp = (wid & 1) * 64;
    const int nwarp = (wid >> 1) * 64;
    const int rA = ((sel & 1) << 3) + l7;            // A: sel0,2 -> rows 0-7; sel1,3 -> rows 8-15
    const uint32_t kbA = (uint32_t)(sel >> 1) << 4;  // A: sel2,3 -> k+8 (16B)
    const int rB = (((sel >> 1) & 1) << 3) + l7;     // B: sel2,3 -> n+8
    const uint32_t kbB = (uint32_t)(sel & 1) << 4;   // B: sel1,3 -> k+8
    uint32_t rowA[4], rowB[4];
    #pragma unroll
    for (int f = 0; f < 4; f++) rowA[f] = (uint32_t)(mwarp + f * 16 + rA) * 128u;
    #pragma unroll
    for (int g = 0; g < 4; g++) rowB[g] = (uint32_t)(nwarp + g * 16 + rB) * 128u + (uint32_t)A_BYTES;

    uint32_t g = 0;                                  // global chunk counter (ring position)
    #pragma unroll 1
    for (int tl = 0; tl < ntiles; tl++) {
        const int t  = bid + tl * gsz;               // lockstep waves: good L2 tile sharing
        const int m0 = (t >> 4) * TILE_M;
        const int n0 = (t & 15) * TILE_N;

        float d[4][8][4] = {};

        #pragma unroll 1
        for (int i = 0; i < NCHUNKS; i++, g++) {
            const uint32_t s  = g & (STAGES - 1);
            const uint32_t ph = (g >> 2) & 1u;
            MBAR_WAIT(sb + OFF_FULL(s), ph);
            const uint32_t st = sb + SMEM_CTRL + s * STAGE_BYTES;

            #pragma unroll
            for (int kk = 0; kk < KCHUNK / 16; kk++) {
                const uint32_t kb = (uint32_t)kk << 5;          // kk*32 bytes
                uint32_t bb[4][4], aa[4][4];
                #pragma unroll
                for (int gg = 0; gg < 4; gg++) ldsm4(bb[gg], st + rowB[gg] + ((kb + kbB) ^ xm));
                #pragma unroll
                for (int f = 0; f < 4; f++) ldsm4(aa[f], st + rowA[f] + ((kb + kbA) ^ xm));
                #pragma unroll
                for (int f = 0; f < 4; f++)
                    #pragma unroll
                    for (int gg = 0; gg < 4; gg++) {
                        mma16816(d[f][2 * gg],     aa[f], &bb[gg][0]);
                        mma16816(d[f][2 * gg + 1], aa[f], &bb[gg][2]);
                    }
            }

            __syncwarp();
            if (lane == 0) MBAR_ARRIVE(sb + OFF_EMPTY(s));

            // producer: refill this slot with chunk g+STAGES (may belong to next tile)
            if (tid == 0 && g + STAGES < totalChunks) {
                MBAR_WAIT(sb + OFF_EMPTY(s), ph);               // completion #(g>>2) on this slot
                const uint32_t f  = g + STAGES;
                const int ftl     = (int)(f >> 6);              // f / NCHUNKS
                const int fch     = (int)(f & 63);
                const int ft      = bid + ftl * gsz;
                const int fm0     = (ft >> 4) * TILE_M;
                const int fn0     = (ft & 15) * TILE_N;
                MBAR_EXPECT_TX(sb + OFF_FULL(s), STAGE_BYTES);
                tma2d(st,           &tm_x, fch * KCHUNK, fm0, sb + OFF_FULL(s));
                tma2d(st + A_BYTES, &tm_w, fch * KCHUNK, fn0, sb + OFF_FULL(s));
            }
        }

        // ---- epilogue: registers -> gmem, add bias (overlaps next tile's TMAs) ----
        const int g2 = lane >> 2, tg = lane & 3;
        float bv0[8], bv1[8];
        #pragma unroll
        for (int nf = 0; nf < 8; nf++) {
            const int n = n0 + nwarp + nf * 8 + tg * 2;
            bv0[nf] = bias[n];
            bv1[nf] = bias[n + 1];
        }
        #pragma unroll
        for (int f = 0; f < 4; f++) {
            const int mrow = m0 + mwarp + f * 16 + g2;
            #pragma unroll
            for (int nf = 0; nf < 8; nf++) {
                const int n = n0 + nwarp + nf * 8 + tg * 2;
                float2 v0 = make_float2(d[f][nf][0] + bv0[nf], d[f][nf][1] + bv1[nf]);
                float2 v1 = make_float2(d[f][nf][2] + bv0[nf], d[f][nf][3] + bv1[nf]);
                *reinterpret_cast<float2*>(&out[(size_t)mrow * N_DIM + n]) = v0;
                *reinterpret_cast<float2*>(&out[(size_t)(mrow + 8) * N_DIM + n]) = v1;
            }
        }
    }
}

// ---------------- host ----------------
typedef CUresult (*PFN_EncodeTiled)(
    CUtensorMap*, CUtensorMapDataType, cuuint32_t, void*,
    const cuuint64_t*, const cuuint64_t*, const cuuint32_t*, const cuuint32_t*,
    CUtensorMapInterleave, CUtensorMapSwizzle, CUtensorMapL2promotion, CUtensorMapFloatOOBfill);

static void make_map_2d(PFN_EncodeTiled fn, CUtensorMap* m, void* ptr,
                        uint64_t rows, uint32_t boxRows) {
    cuuint64_t dims[2]    = {(cuuint64_t)K_DIM, (cuuint64_t)rows};
    cuuint64_t strides[1] = {(cuuint64_t)K_DIM * 2};
    cuuint32_t box[2]     = {(cuuint32_t)KCHUNK, boxRows};   // 64 fp16 = 128B (SW128 limit)
    cuuint32_t es[2]      = {1, 1};
    fn(m, CU_TENSOR_MAP_DATA_TYPE_FLOAT16, 2, ptr, dims, strides, box, es,
       CU_TENSOR_MAP_INTERLEAVE_NONE, CU_TENSOR_MAP_SWIZZLE_128B,
       CU_TENSOR_MAP_L2_PROMOTION_L2_128B, CU_TENSOR_MAP_FLOAT_OOB_FILL_NONE);
}

extern "C" void kernel_launch(void* const* d_in, const int* in_sizes, int n_in,
                              void* d_out, int out_size) {
    const float* x    = (const float*)d_in[0];
    const float* w    = (const float*)d_in[1];
    const float* bias = (const float*)d_in[2];
    float* out = (float*)d_out;

    void *p_wdq, *p_xh;
    cudaGetSymbolAddress(&p_wdq, g_wdq);
    cudaGetSymbolAddress(&p_xh, g_xh);

    // 1) fused: quantize W -> exact fp16 plane, convert x -> fp16
    prep_kernel<<<QUANT_BLOCKS + CONV_BLOCKS, 256>>>(
        (const float4*)w, (uint4*)p_wdq, (const float4*)x, (uint4*)p_xh);

    // 2) tensor maps (host-side; happens at graph-capture time, free at replay)
    PFN_EncodeTiled fn = nullptr;
    cudaDriverEntryPointQueryResult qres;
    cudaGetDriverEntryPointByVersion("cuTensorMapEncodeTiled", (void**)&fn, 12000,
                                     cudaEnableDefault, &qres);
    if (!fn) return;

    CUtensorMap tm_x, tm_w;
    make_map_2d(fn, &tm_x, p_xh,  M_DIM, TILE_M);
    make_map_2d(fn, &tm_w, p_wdq, N_DIM, TILE_N);

    cudaFuncSetAttribute(gemm_kernel, cudaFuncAttributeMaxDynamicSharedMemorySize, SMEM_REQ);
    gemm_kernel<<<GRID_SM, 256, SMEM_REQ>>>(tm_x, tm_w, bias, out);
}